// round 13
// baseline (speedup 1.0000x reference)
#include <cuda_runtime.h>
#include <cuda_bf16.h>
#include <cstdint>
#include <math.h>

#define T_STEPS 32
#define B_SZ    512
#define S_SZ    64
#define F_INDIM 128
#define H1      256
#define H2      256
#define H3      128
#define M_ROWS  (T_STEPS * B_SZ)   // 16384

__device__ __nv_bfloat16 g_spk0[M_ROWS * F_INDIM];
__device__ __nv_bfloat16 g_spk1[M_ROWS * H1];
__device__ __nv_bfloat16 g_spk2[M_ROWS * H2];
__device__ __nv_bfloat16 g_W1s[3 * H1 * F_INDIM];   // [split][h][i]
__device__ __nv_bfloat16 g_W2s[3 * H2 * H1];
__device__ __nv_bfloat16 g_W3s[3 * H3 * H2];

__device__ __forceinline__ uint32_t smem_u32(const void* p) {
    uint32_t a;
    asm("{ .reg .u64 t; cvta.to.shared.u64 t, %1; cvt.u32.u64 %0, t; }" : "=r"(a) : "l"(p));
    return a;
}
__device__ __forceinline__ void ldsm4(uint32_t& r0, uint32_t& r1, uint32_t& r2,
                                      uint32_t& r3, uint32_t addr) {
    asm volatile("ldmatrix.sync.aligned.m8n8.x4.shared.b16 {%0,%1,%2,%3}, [%4];"
                 : "=r"(r0), "=r"(r1), "=r"(r2), "=r"(r3) : "r"(addr));
}
__device__ __forceinline__ void mma16816(float* c, const uint32_t* a,
                                         uint32_t b0, uint32_t b1) {
    asm volatile(
        "mma.sync.aligned.m16n8k16.row.col.f32.bf16.bf16.f32 "
        "{%0,%1,%2,%3}, {%4,%5,%6,%7}, {%8,%9}, {%0,%1,%2,%3};"
        : "+f"(c[0]), "+f"(c[1]), "+f"(c[2]), "+f"(c[3])
        : "r"(a[0]), "r"(a[1]), "r"(a[2]), "r"(a[3]), "r"(b0), "r"(b1));
}
__device__ __forceinline__ void cp16(uint32_t dst, const void* src) {
    asm volatile("cp.async.cg.shared.global [%0], [%1], 16;" :: "r"(dst), "l"(src));
}
#define CP_COMMIT() asm volatile("cp.async.commit_group;" ::: "memory")
#define CP_WAIT(n)  asm volatile("cp.async.wait_group %0;" :: "n"(n) : "memory")

// ---------------------------------------------------------------------------
// Merged encoder + weight-split kernel.
//   blocks [0, 512):   latency encoder (one block per batch element)
//   blocks [512, 768): bf16 3-way weight splits
//
// Encoder classification: t = rint(logf(d/(d-0.01))*31/TMAX) is a monotone
// binning of d. Per CTA, threads 0..30 compute window edges [WLO_k, WHI_k]
// (double precision, +-1e-3 in t-space, widened 2 ulps) around each boundary.
// Per value: t = count(WLO_k > d) when count(WLO_k > d) == count(WHI_k >= d)
// (provably equal to the reference's t outside the windows); otherwise
// (~0.2% of values) evaluate the reference float expression verbatim.
// Output is bit-identical to per-value logf evaluation, at ALU cost not MUFU.
// ---------------------------------------------------------------------------
__global__ void __launch_bounds__(512)
encode_split_kernel(const float* __restrict__ x, __nv_bfloat16* __restrict__ out,
                    const float* __restrict__ W1, const float* __restrict__ W2,
                    const float* __restrict__ W3,
                    __nv_bfloat16* __restrict__ o1, __nv_bfloat16* __restrict__ o2,
                    __nv_bfloat16* __restrict__ o3) {
    const int tid = threadIdx.x;

    if (blockIdx.x >= 512) {    // ---- weight-split blocks ----
        const int n1 = H1 * F_INDIM, n2 = H2 * H1, n3 = H3 * H2;
        int idx = (blockIdx.x - 512) * 512 + tid;
        const float* W; __nv_bfloat16* o; int n, i;
        if (idx < n1)                { W = W1; o = o1; n = n1; i = idx; }
        else if (idx < n1 + n2)      { W = W2; o = o2; n = n2; i = idx - n1; }
        else if (idx < n1 + n2 + n3) { W = W3; o = o3; n = n3; i = idx - n1 - n2; }
        else return;
        float w = W[i];
        __nv_bfloat16 h1 = __float2bfloat16_rn(w);
        float r1 = w - __bfloat162float(h1);
        __nv_bfloat16 h2 = __float2bfloat16_rn(r1);
        float r2 = r1 - __bfloat162float(h2);
        o[i] = h1; o[n + i] = h2; o[2 * n + i] = __float2bfloat16_rn(r2);
        return;
    }

    // ---- encoder blocks ----
    __shared__ float sWLO[32], sWHI[32];

    const float TMAX = 11.512935464920229f;   // np.float32(log((0.01+1e-7)/1e-7))

    if (tid < 31) {
        double L = (double)TMAX / 31.0;
        double tm = (double)tid + 0.5;
        double Em  = exp(tm * L);
        double Ehi = exp((tm + 1e-3) * L);
        double Elo = exp((tm - 1e-3) * L);
        float  Df  = (float)(0.01 * Em  / (Em  - 1.0));
        float  dlo = (float)(0.01 * Ehi / (Ehi - 1.0));   // smaller d
        float  dhi = (float)(0.01 * Elo / (Elo - 1.0));   // larger d
        float wlo = fminf(dlo, Df);
        float whi = fmaxf(dhi, Df);
        wlo = nextafterf(nextafterf(wlo, 0.0f), 0.0f);
        whi = nextafterf(nextafterf(whi, 2.0f), 2.0f);
        sWLO[tid] = wlo;
        sWHI[tid] = whi;
    }
    __syncthreads();

    auto classify = [&](float xn) -> int {
        float d = fmaxf(xn, 0.0100001f);
        int cLO = 0, cHI = 0;
#pragma unroll
        for (int k = 0; k < 31; ++k) {
            cLO += (sWLO[k] > d)  ? 1 : 0;
            cHI += (sWHI[k] >= d) ? 1 : 0;
        }
        int t = cLO;
        if (cLO != cHI) {   // ambiguous: reference float expression verbatim
            float lg = logf(d / (d - 0.01f));
            float tr = rintf((lg * 31.0f) / TMAX);
            tr = fminf(fmaxf(tr, 0.0f), 31.0f);
            t = (int)tr;
        }
        return t;
    };

    const int b = blockIdx.x;
    const int f = tid >> 2;
    const int j = tid & 3;

    const float* xp = x + (size_t)b * (S_SZ * F_INDIM) + f;

    float mn = 1e30f, mx = -1e30f;
    unsigned mask = 0;
#pragma unroll
    for (int s = 0; s < 16; ++s) {
        float raw = xp[(j * 16 + s) * F_INDIM];
        float g = (raw < 0.75f) ? 0.0f : raw;
        mn = fminf(mn, g);
        mx = fmaxf(mx, g);
        mask |= (g != 0.0f) ? (1u << s) : 0u;
    }
    mn = fminf(mn, __shfl_xor_sync(0xFFFFFFFFu, mn, 1));
    mn = fminf(mn, __shfl_xor_sync(0xFFFFFFFFu, mn, 2));
    mx = fmaxf(mx, __shfl_xor_sync(0xFFFFFFFFu, mx, 1));
    mx = fmaxf(mx, __shfl_xor_sync(0xFFFFFFFFu, mx, 2));

    float denom = mx - mn + 1e-8f;

    unsigned pk[8];
#pragma unroll
    for (int i = 0; i < 8; ++i) pk[i] = 0u;

    int zc = 16 - __popc(mask);
    if (zc) {
        int t = classify((0.0f - mn) / denom);
        pk[t >> 2] += (unsigned)zc << ((t & 3) * 8);
    }
    while (mask) {
        int s = __ffs(mask) - 1;
        mask &= mask - 1;
        float v = xp[(j * 16 + s) * F_INDIM];   // L1 hit
        int t = classify((v - mn) / denom);
        pk[t >> 2] += 1u << ((t & 3) * 8);
    }

#pragma unroll
    for (int i = 0; i < 8; ++i) {
        pk[i] += __shfl_xor_sync(0xFFFFFFFFu, pk[i], 1);
        pk[i] += __shfl_xor_sync(0xFFFFFFFFu, pk[i], 2);
    }
#pragma unroll
    for (int i = 0; i < 8; ++i) {
        int t = j * 8 + i;
        unsigned c = (pk[t >> 2] >> ((t & 3) * 8)) & 0xFFu;
        out[((size_t)b * T_STEPS + t) * F_INDIM + f] =
            __float2bfloat16_rn((float)c * (1.0f / 64.0f));
    }
}

// ---------------------------------------------------------------------------
// Fused HMMA GEMM + LIF (R11-proven compute, templated pipeline depth).
// NWM m-warps x (16/NWM) n-warps; warp tile (TM/NWM)m x (128/NWN)n. KC=64.
// ---------------------------------------------------------------------------
template <int IN, int H, int TM, int NWM, int STAGES, bool TMAJ, bool ONESHOT>
__global__ void __launch_bounds__(512, 1)
layer_hmma(const __nv_bfloat16* __restrict__ in,
           const __nv_bfloat16* __restrict__ Wsp,
           const float* __restrict__ bias,
           __nv_bfloat16* __restrict__ out_bf,
           float* __restrict__ out_f) {
    constexpr int KC      = 64;
    constexpr int NWN     = 16 / NWM;
    constexpr int WN      = 128 / NWN;
    constexpr int NB      = WN / 16;
    constexpr int MB      = TM / (16 * NWM);
    constexpr int A_BYTES = TM * 128;
    constexpr int B_SPLIT = 128 * 128;
    constexpr int SS      = A_BYTES + 3 * B_SPLIT;
    constexpr int NCH     = IN / KC;

    extern __shared__ __align__(1024) char smem[];
    const uint32_t sbase = smem_u32(smem);

    const int tid  = threadIdx.x;
    const int lane = tid & 31;
    const int wrp  = tid >> 5;
    const int wm   = wrp / NWN;
    const int wn   = wrp % NWN;
    const int r0   = blockIdx.x * TM;
    const int N0   = blockIdx.y * 128;

    const int la_row = lane & 15;
    const int la_ch  = lane >> 4;
    const int lb_row = lane & 7;
    const int lb_ns  = lane >> 4;
    const int lb_ch  = (lane >> 3) & 1;

    int mrow[MB], nrow[NB];
#pragma unroll
    for (int mb = 0; mb < MB; ++mb) mrow[mb] = wm * (TM / NWM) + mb * 16 + la_row;
#pragma unroll
    for (int p = 0; p < NB; ++p) nrow[p] = wn * WN + p * 16 + lb_ns * 8 + lb_row;

    const __nv_bfloat16* Ag = in + (size_t)r0 * IN;

    auto issue_stage = [&](int ch, int buf) {
        const uint32_t dstA = sbase + buf * SS;
#pragma unroll
        for (int it = 0; it < TM / 64; ++it) {
            int v = tid + it * 512, m = v >> 3, kv = v & 7;
            uint32_t off = (uint32_t)(m * 128 + kv * 16);
            off ^= (off >> 3) & 0x70;
            cp16(dstA + off, Ag + (size_t)m * IN + ch * KC + kv * 8);
        }
        const uint32_t dstB = dstA + A_BYTES;
#pragma unroll
        for (int it = 0; it < 6; ++it) {
            int v = tid + it * 512, s = v >> 10, w = v & 1023, n = w >> 3, kv = w & 7;
            uint32_t off = (uint32_t)(n * 128 + kv * 16);
            off ^= (off >> 3) & 0x70;
            cp16(dstB + s * B_SPLIT + off,
                 Wsp + (size_t)s * H * IN + (size_t)(N0 + n) * IN + ch * KC + kv * 8);
        }
        CP_COMMIT();
    };

    float c[MB][NB * 2][4];
#pragma unroll
    for (int mb = 0; mb < MB; ++mb)
#pragma unroll
        for (int nb = 0; nb < NB * 2; ++nb)
#pragma unroll
            for (int q = 0; q < 4; ++q) c[mb][nb][q] = 0.0f;

    auto compute_chunk = [&](uint32_t bufA, uint32_t bufB) {
        uint32_t aF[2][MB][4];
        uint32_t bF[2][NB][4];

        auto loadA = [&](int ks, int pb) {
#pragma unroll
            for (int mb = 0; mb < MB; ++mb) {
                uint32_t off = (uint32_t)(mrow[mb] * 128 +
                               (((ks * 2 + la_ch) * 16) ^ ((mrow[mb] & 7) << 4)));
                ldsm4(aF[pb][mb][0], aF[pb][mb][1], aF[pb][mb][2], aF[pb][mb][3],
                      bufA + off);
            }
        };
        auto loadB = [&](int ks, int s, int pb) {
#pragma unroll
            for (int p = 0; p < NB; ++p) {
                uint32_t off = (uint32_t)(nrow[p] * 128 +
                               (((ks * 2 + lb_ch) * 16) ^ ((nrow[p] & 7) << 4)));
                ldsm4(bF[pb][p][0], bF[pb][p][1], bF[pb][p][2], bF[pb][p][3],
                      bufB + s * B_SPLIT + off);
            }
        };

        loadA(0, 0);
        loadB(0, 0, 0);
#pragma unroll
        for (int u = 0; u < 12; ++u) {
            const int ks = u / 3;
            const int pb = u & 1;
            if (u < 11) {
                const int un = u + 1;
                const int ksn = un / 3, sn = un - ksn * 3;
                loadB(ksn, sn, un & 1);
                if (sn == 0) loadA(ksn, ksn & 1);
            }
#pragma unroll
            for (int p = 0; p < NB; ++p) {
#pragma unroll
                for (int mb = 0; mb < MB; ++mb) {
                    mma16816(c[mb][2 * p + 0], aF[ks & 1][mb], bF[pb][p][0], bF[pb][p][1]);
                    mma16816(c[mb][2 * p + 1], aF[ks & 1][mb], bF[pb][p][2], bF[pb][p][3]);
                }
            }
        }
    };

    if (ONESHOT) {
#pragma unroll
        for (int ch = 0; ch < NCH; ++ch) issue_stage(ch, ch);
        CP_WAIT(0);
        __syncthreads();
#pragma unroll
        for (int ch = 0; ch < NCH; ++ch)
            compute_chunk(sbase + ch * SS, sbase + ch * SS + A_BYTES);
        __syncthreads();
    } else {
        constexpr int PRE = (STAGES - 1 < NCH) ? STAGES - 1 : NCH;
#pragma unroll
        for (int ch = 0; ch < PRE; ++ch) issue_stage(ch, ch % STAGES);
#pragma unroll 1
        for (int ch = 0; ch < NCH; ++ch) {
            if (ch + PRE < NCH) {
                issue_stage(ch + PRE, (ch + PRE) % STAGES);
                CP_WAIT(STAGES - 1);
            } else {
                CP_WAIT(0);
            }
            __syncthreads();
            const uint32_t bufA = sbase + (ch % STAGES) * SS;
            compute_chunk(bufA, bufA + A_BYTES);
            __syncthreads();
        }
    }

    // ---- epilogue: C frags -> smem [TM m][132 stride] f32 ----
    float* scur = (float*)smem;
#pragma unroll
    for (int mb = 0; mb < MB; ++mb)
#pragma unroll
        for (int nb = 0; nb < NB * 2; ++nb) {
            int row = wm * (TM / NWM) + mb * 16 + (lane >> 2);
            int col = wn * WN + nb * 8 + 2 * (lane & 3);
            *(float2*)&scur[(size_t)row * 132 + col] =
                make_float2(c[mb][nb][0], c[mb][nb][1]);
            *(float2*)&scur[(size_t)(row + 8) * 132 + col] =
                make_float2(c[mb][nb][2], c[mb][nb][3]);
        }
    __syncthreads();

    // ---- fused LIF scan ----
#pragma unroll
    for (int task = tid; task < (TM / 32) * 128; task += 512) {
        const int bl = task >> 7;
        const int h  = task & 127;
        const float bv = bias[N0 + h];
        const int bglob = blockIdx.x * (TM / 32) + bl;
        float mem = 0.0f;
#pragma unroll
        for (int t = 0; t < T_STEPS; ++t) {
            float a2  = scur[(size_t)(bl * 32 + t) * 132 + h];
            float cur = __fadd_rn(a2, bv);
            float r   = (mem > 1.0f) ? 1.0f : 0.0f;
            mem = __fsub_rn(__fadd_rn(__fmul_rn(0.9f, mem), cur), r);
            float spk = (mem > 1.0f) ? 1.0f : 0.0f;
            if (TMAJ) {
                out_f[((size_t)t * B_SZ + bglob) * H + N0 + h] = spk;
            } else {
                out_bf[(size_t)(r0 + bl * 32 + t) * H + N0 + h] = __float2bfloat16_rn(spk);
            }
        }
    }
}

// ---------------------------------------------------------------------------
extern "C" void kernel_launch(void* const* d_in, const int* in_sizes, int n_in,
                              void* d_out, int out_size) {
    const float* x  = (const float*)d_in[0];
    const float* W1 = (const float*)d_in[1];
    const float* b1 = (const float*)d_in[2];
    const float* W2 = (const float*)d_in[3];
    const float* b2 = (const float*)d_in[4];
    const float* W3 = (const float*)d_in[5];
    const float* b3 = (const float*)d_in[6];
    float* out = (float*)d_out;

    __nv_bfloat16 *spk0, *spk1, *spk2, *w1s, *w2s, *w3s;
    cudaGetSymbolAddress((void**)&spk0, g_spk0);
    cudaGetSymbolAddress((void**)&spk1, g_spk1);
    cudaGetSymbolAddress((void**)&spk2, g_spk2);
    cudaGetSymbolAddress((void**)&w1s, g_W1s);
    cudaGetSymbolAddress((void**)&w2s, g_W2s);
    cudaGetSymbolAddress((void**)&w3s, g_W3s);

    constexpr int SS256 = 256 * 128 + 3 * 16384;   // 81920
    constexpr int SS128 = 128 * 128 + 3 * 16384;   // 65536
    constexpr int SM_L1 = 2 * SS256;               // 163840 (ONESHOT, NCH=2)
    constexpr int SM_L2 = 2 * SS256;               // 163840 (2-stage)
    constexpr int SM_L3 = 3 * SS128;               // 196608 (3-stage)

    cudaFuncSetAttribute((const void*)layer_hmma<F_INDIM, H1, 256, 4, 2, false, true>,
                         cudaFuncAttributeMaxDynamicSharedMemorySize, SM_L1);
    cudaFuncSetAttribute((const void*)layer_hmma<H1, H2, 256, 4, 2, false, false>,
                         cudaFuncAttributeMaxDynamicSharedMemorySize, SM_L2);
    cudaFuncSetAttribute((const void*)layer_hmma<H2, H3, 128, 4, 3, true, false>,
                         cudaFuncAttributeMaxDynamicSharedMemorySize, SM_L3);

    encode_split_kernel<<<512 + 256, 512>>>(x, spk0, W1, W2, W3, w1s, w2s, w3s);

    layer_hmma<F_INDIM, H1, 256, 4, 2, false, true>
        <<<dim3(M_ROWS / 256, H1 / 128), 512, SM_L1>>>(spk0, w1s, b1, spk1, nullptr);
    layer_hmma<H1, H2, 256, 4, 2, false, false>
        <<<dim3(M_ROWS / 256, H2 / 128), 512, SM_L2>>>(spk1, w2s, b2, spk2, nullptr);
    layer_hmma<H2, H3, 128, 4, 3, true, false>
        <<<dim3(M_ROWS / 128, H3 / 128), 512, SM_L3>>>(spk2, w3s, b3, nullptr, out);
}

// round 14
// speedup vs baseline: 1.3229x; 1.3229x over previous
#include <cuda_runtime.h>
#include <cuda_bf16.h>
#include <cstdint>

#define T_STEPS 32
#define B_SZ    512
#define S_SZ    64
#define F_INDIM 128
#define H1      256
#define H2      256
#define H3      128
#define M_ROWS  (T_STEPS * B_SZ)   // 16384

__device__ __nv_bfloat16 g_spk0[M_ROWS * F_INDIM];
__device__ __nv_bfloat16 g_spk1[M_ROWS * H1];
__device__ __nv_bfloat16 g_spk2[M_ROWS * H2];
__device__ __nv_bfloat16 g_W1s[3 * H1 * F_INDIM];   // [split][h][i]
__device__ __nv_bfloat16 g_W2s[3 * H2 * H1];
__device__ __nv_bfloat16 g_W3s[3 * H3 * H2];

__device__ __forceinline__ uint32_t smem_u32(const void* p) {
    uint32_t a;
    asm("{ .reg .u64 t; cvta.to.shared.u64 t, %1; cvt.u32.u64 %0, t; }" : "=r"(a) : "l"(p));
    return a;
}
__device__ __forceinline__ void ldsm4(uint32_t& r0, uint32_t& r1, uint32_t& r2,
                                      uint32_t& r3, uint32_t addr) {
    asm volatile("ldmatrix.sync.aligned.m8n8.x4.shared.b16 {%0,%1,%2,%3}, [%4];"
                 : "=r"(r0), "=r"(r1), "=r"(r2), "=r"(r3) : "r"(addr));
}
__device__ __forceinline__ void mma16816(float* c, const uint32_t* a,
                                         uint32_t b0, uint32_t b1) {
    asm volatile(
        "mma.sync.aligned.m16n8k16.row.col.f32.bf16.bf16.f32 "
        "{%0,%1,%2,%3}, {%4,%5,%6,%7}, {%8,%9}, {%0,%1,%2,%3};"
        : "+f"(c[0]), "+f"(c[1]), "+f"(c[2]), "+f"(c[3])
        : "r"(a[0]), "r"(a[1]), "r"(a[2]), "r"(a[3]), "r"(b0), "r"(b1));
}
__device__ __forceinline__ void cp16(uint32_t dst, const void* src) {
    asm volatile("cp.async.cg.shared.global [%0], [%1], 16;" :: "r"(dst), "l"(src));
}
#define CP_COMMIT() asm volatile("cp.async.commit_group;" ::: "memory")
#define CP_WAIT(n)  asm volatile("cp.async.wait_group %0;" :: "n"(n) : "memory")

// ---------------------------------------------------------------------------
// Merged encoder + weight-split kernel, 1024 threads/CTA.
//   blocks [0, 512):   latency encoder (one block per batch element; 8 j-lanes
//                      per feature, 8 values/thread — R6 math verbatim)
//   blocks [512, 640): bf16 3-way weight splits (1024 elems per block)
// ---------------------------------------------------------------------------
__global__ void __launch_bounds__(1024)
encode_split_kernel(const float* __restrict__ x, __nv_bfloat16* __restrict__ out,
                    const float* __restrict__ W1, const float* __restrict__ W2,
                    const float* __restrict__ W3,
                    __nv_bfloat16* __restrict__ o1, __nv_bfloat16* __restrict__ o2,
                    __nv_bfloat16* __restrict__ o3) {
    const int tid = threadIdx.x;

    if (blockIdx.x >= 512) {    // ---- weight-split blocks ----
        const int n1 = H1 * F_INDIM, n2 = H2 * H1, n3 = H3 * H2;
        int idx = (blockIdx.x - 512) * 1024 + tid;
        const float* W; __nv_bfloat16* o; int n, i;
        if (idx < n1)                { W = W1; o = o1; n = n1; i = idx; }
        else if (idx < n1 + n2)      { W = W2; o = o2; n = n2; i = idx - n1; }
        else if (idx < n1 + n2 + n3) { W = W3; o = o3; n = n3; i = idx - n1 - n2; }
        else return;
        float w = W[i];
        __nv_bfloat16 h1 = __float2bfloat16_rn(w);
        float r1 = w - __bfloat162float(h1);
        __nv_bfloat16 h2 = __float2bfloat16_rn(r1);
        float r2 = r1 - __bfloat162float(h2);
        o[i] = h1; o[n + i] = h2; o[2 * n + i] = __float2bfloat16_rn(r2);
        return;
    }

    // ---- encoder blocks: thread (f, j), j in [0,8), handles s = j*8..j*8+7 ----
    const int b = blockIdx.x;
    const int f = tid >> 3;
    const int j = tid & 7;

    const float* xp = x + (size_t)b * (S_SZ * F_INDIM) + f;

    float mn = 1e30f, mx = -1e30f;
    unsigned mask = 0;
#pragma unroll
    for (int s = 0; s < 8; ++s) {
        float raw = xp[(j * 8 + s) * F_INDIM];
        float g = (raw < 0.75f) ? 0.0f : raw;
        mn = fminf(mn, g);
        mx = fmaxf(mx, g);
        mask |= (g != 0.0f) ? (1u << s) : 0u;
    }
    // merge across the 8 j-lanes (lane = (f&3)*8 + j, xor 1/2/4 stays in-group)
    mn = fminf(mn, __shfl_xor_sync(0xFFFFFFFFu, mn, 1));
    mn = fminf(mn, __shfl_xor_sync(0xFFFFFFFFu, mn, 2));
    mn = fminf(mn, __shfl_xor_sync(0xFFFFFFFFu, mn, 4));
    mx = fmaxf(mx, __shfl_xor_sync(0xFFFFFFFFu, mx, 1));
    mx = fmaxf(mx, __shfl_xor_sync(0xFFFFFFFFu, mx, 2));
    mx = fmaxf(mx, __shfl_xor_sync(0xFFFFFFFFu, mx, 4));

    float denom = mx - mn + 1e-8f;
    const float TMAX = 11.512935464920229f;

    unsigned pk[8];
#pragma unroll
    for (int i = 0; i < 8; ++i) pk[i] = 0u;

    int zc = 8 - __popc(mask);
    if (zc) {
        float xn = (0.0f - mn) / denom;
        float d  = fmaxf(xn, 0.0100001f);
        float lg = logf(d / (d - 0.01f));
        float tr = rintf((lg * 31.0f) / TMAX);
        tr = fminf(fmaxf(tr, 0.0f), 31.0f);
        int t = (int)tr;
        pk[t >> 2] += (unsigned)zc << ((t & 3) * 8);
    }
    while (mask) {
        int s = __ffs(mask) - 1;
        mask &= mask - 1;
        float v  = xp[(j * 8 + s) * F_INDIM];
        float xn = (v - mn) / denom;
        float d  = fmaxf(xn, 0.0100001f);
        float lg = logf(d / (d - 0.01f));
        float tr = rintf((lg * 31.0f) / TMAX);
        tr = fminf(fmaxf(tr, 0.0f), 31.0f);
        int t = (int)tr;
        pk[t >> 2] += 1u << ((t & 3) * 8);
    }

#pragma unroll
    for (int i = 0; i < 8; ++i) {
        pk[i] += __shfl_xor_sync(0xFFFFFFFFu, pk[i], 1);
        pk[i] += __shfl_xor_sync(0xFFFFFFFFu, pk[i], 2);
        pk[i] += __shfl_xor_sync(0xFFFFFFFFu, pk[i], 4);
    }
    // lane j writes t = j*4 .. j*4+3
#pragma unroll
    for (int i = 0; i < 4; ++i) {
        int t = j * 4 + i;
        unsigned c = (pk[t >> 2] >> ((t & 3) * 8)) & 0xFFu;
        out[((size_t)b * T_STEPS + t) * F_INDIM + f] =
            __float2bfloat16_rn((float)c * (1.0f / 64.0f));
    }
}

// ---------------------------------------------------------------------------
// Fused HMMA GEMM + LIF — R11 champion configuration verbatim:
// tile TM x 128, 512 threads (16 warps: 4m x 4n), warp tile (TM/4)m x 32n,
// MB = TM/64, KC=64, register-double-buffered SWP over 12 steps.
// ONESHOT (layer 1): stage all K upfront. Else cp.async 2-stage.
// ---------------------------------------------------------------------------
template <int IN, int H, int TM, bool TMAJ, bool ONESHOT>
__global__ void __launch_bounds__(512, 1)
layer_hmma(const __nv_bfloat16* __restrict__ in,
           const __nv_bfloat16* __restrict__ Wsp,
           const float* __restrict__ bias,
           __nv_bfloat16* __restrict__ out_bf,
           float* __restrict__ out_f) {
    constexpr int A_BYTES = TM * 128;
    constexpr int SS      = A_BYTES + 3 * 16384;
    constexpr int MB      = TM / 64;
    constexpr int NCH     = IN / 64;

    extern __shared__ __align__(1024) char smem[];
    const uint32_t sbase = smem_u32(smem);

    const int tid  = threadIdx.x;
    const int lane = tid & 31;
    const int wrp  = tid >> 5;
    const int wm   = wrp & 3;
    const int wn   = wrp >> 2;
    const int r0   = blockIdx.x * TM;
    const int N0   = blockIdx.y * 128;

    const int la_row = lane & 15;
    const int la_ch  = lane >> 4;
    const int lb_row = lane & 7;
    const int lb_ns  = lane >> 4;
    const int lb_ch  = (lane >> 3) & 1;

    int mrow[MB], nrow[2];
#pragma unroll
    for (int mb = 0; mb < MB; ++mb) mrow[mb] = wm * (TM / 4) + mb * 16 + la_row;
#pragma unroll
    for (int p = 0; p < 2; ++p) nrow[p] = wn * 32 + p * 16 + lb_ns * 8 + lb_row;

    const __nv_bfloat16* Ag = in + (size_t)r0 * IN;

    auto issue_stage = [&](int ch, int buf) {
        const uint32_t dstA = sbase + buf * SS;
#pragma unroll
        for (int it = 0; it < TM / 64; ++it) {
            int v = tid + it * 512, m = v >> 3, kv = v & 7;
            uint32_t off = (uint32_t)(m * 128 + kv * 16);
            off ^= (off >> 3) & 0x70;
            cp16(dstA + off, Ag + (size_t)m * IN + ch * 64 + kv * 8);
        }
        const uint32_t dstB = dstA + A_BYTES;
#pragma unroll
        for (int it = 0; it < 6; ++it) {
            int v = tid + it * 512, s = v >> 10, w = v & 1023, n = w >> 3, kv = w & 7;
            uint32_t off = (uint32_t)(n * 128 + kv * 16);
            off ^= (off >> 3) & 0x70;
            cp16(dstB + s * 16384 + off,
                 Wsp + (size_t)s * H * IN + (size_t)(N0 + n) * IN + ch * 64 + kv * 8);
        }
        CP_COMMIT();
    };

    float c[MB][4][4];
#pragma unroll
    for (int mb = 0; mb < MB; ++mb)
#pragma unroll
        for (int nb = 0; nb < 4; ++nb)
#pragma unroll
            for (int q = 0; q < 4; ++q) c[mb][nb][q] = 0.0f;

    auto compute_chunk = [&](uint32_t bufA, uint32_t bufB) {
        uint32_t aF[2][MB][4];
        uint32_t bF[2][2][4];

        auto loadA = [&](int ks, int pb) {
#pragma unroll
            for (int mb = 0; mb < MB; ++mb) {
                uint32_t off = (uint32_t)(mrow[mb] * 128 +
                               (((ks * 2 + la_ch) * 16) ^ ((mrow[mb] & 7) << 4)));
                ldsm4(aF[pb][mb][0], aF[pb][mb][1], aF[pb][mb][2], aF[pb][mb][3],
                      bufA + off);
            }
        };
        auto loadB = [&](int ks, int s, int pb) {
#pragma unroll
            for (int p = 0; p < 2; ++p) {
                uint32_t off = (uint32_t)(nrow[p] * 128 +
                               (((ks * 2 + lb_ch) * 16) ^ ((nrow[p] & 7) << 4)));
                ldsm4(bF[pb][p][0], bF[pb][p][1], bF[pb][p][2], bF[pb][p][3],
                      bufB + s * 16384 + off);
            }
        };

        loadA(0, 0);
        loadB(0, 0, 0);
#pragma unroll
        for (int u = 0; u < 12; ++u) {
            const int ks = u / 3;
            const int pb = u & 1;
            if (u < 11) {
                const int un = u + 1;
                const int ksn = un / 3, sn = un - ksn * 3;
                loadB(ksn, sn, un & 1);
                if (sn == 0) loadA(ksn, ksn & 1);
            }
#pragma unroll
            for (int p = 0; p < 2; ++p) {
#pragma unroll
                for (int mb = 0; mb < MB; ++mb) {
                    mma16816(c[mb][2 * p + 0], aF[ks & 1][mb], bF[pb][p][0], bF[pb][p][1]);
                    mma16816(c[mb][2 * p + 1], aF[ks & 1][mb], bF[pb][p][2], bF[pb][p][3]);
                }
            }
        }
    };

    if (ONESHOT) {
#pragma unroll
        for (int ch = 0; ch < NCH; ++ch) issue_stage(ch, ch);
        CP_WAIT(0);
        __syncthreads();
#pragma unroll
        for (int ch = 0; ch < NCH; ++ch)
            compute_chunk(sbase + ch * SS, sbase + ch * SS + A_BYTES);
        __syncthreads();
    } else {
        issue_stage(0, 0);
#pragma unroll 1
        for (int ch = 0; ch < NCH; ++ch) {
            if (ch + 1 < NCH) {
                issue_stage(ch + 1, (ch + 1) & 1);
                CP_WAIT(1);
            } else {
                CP_WAIT(0);
            }
            __syncthreads();
            const uint32_t bufA = sbase + (ch & 1) * SS;
            compute_chunk(bufA, bufA + A_BYTES);
            __syncthreads();
        }
    }

    // ---- epilogue: C frags -> smem [TM m][132 stride] f32 ----
    float* scur = (float*)smem;
#pragma unroll
    for (int mb = 0; mb < MB; ++mb)
#pragma unroll
        for (int nb = 0; nb < 4; ++nb) {
            int row = wm * (TM / 4) + mb * 16 + (lane >> 2);
            int col = wn * 32 + nb * 8 + 2 * (lane & 3);
            *(float2*)&scur[(size_t)row * 132 + col] =
                make_float2(c[mb][nb][0], c[mb][nb][1]);
            *(float2*)&scur[(size_t)(row + 8) * 132 + col] =
                make_float2(c[mb][nb][2], c[mb][nb][3]);
        }
    __syncthreads();

    // ---- fused LIF scan ----
#pragma unroll
    for (int task = tid; task < (TM / 32) * 128; task += 512) {
        const int bl = task >> 7;
        const int h  = task & 127;
        const float bv = bias[N0 + h];
        const int bglob = blockIdx.x * (TM / 32) + bl;
        float mem = 0.0f;
#pragma unroll
        for (int t = 0; t < T_STEPS; ++t) {
            float a2  = scur[(size_t)(bl * 32 + t) * 132 + h];
            float cur = __fadd_rn(a2, bv);
            float r   = (mem > 1.0f) ? 1.0f : 0.0f;
            mem = __fsub_rn(__fadd_rn(__fmul_rn(0.9f, mem), cur), r);
            float spk = (mem > 1.0f) ? 1.0f : 0.0f;
            if (TMAJ) {
                out_f[((size_t)t * B_SZ + bglob) * H + N0 + h] = spk;
            } else {
                out_bf[(size_t)(r0 + bl * 32 + t) * H + N0 + h] = __float2bfloat16_rn(spk);
            }
        }
    }
}

// ---------------------------------------------------------------------------
extern "C" void kernel_launch(void* const* d_in, const int* in_sizes, int n_in,
                              void* d_out, int out_size) {
    const float* x  = (const float*)d_in[0];
    const float* W1 = (const float*)d_in[1];
    const float* b1 = (const float*)d_in[2];
    const float* W2 = (const float*)d_in[3];
    const float* b2 = (const float*)d_in[4];
    const float* W3 = (const float*)d_in[5];
    const float* b3 = (const float*)d_in[6];
    float* out = (float*)d_out;

    __nv_bfloat16 *spk0, *spk1, *spk2, *w1s, *w2s, *w3s;
    cudaGetSymbolAddress((void**)&spk0, g_spk0);
    cudaGetSymbolAddress((void**)&spk1, g_spk1);
    cudaGetSymbolAddress((void**)&spk2, g_spk2);
    cudaGetSymbolAddress((void**)&w1s, g_W1s);
    cudaGetSymbolAddress((void**)&w2s, g_W2s);
    cudaGetSymbolAddress((void**)&w3s, g_W3s);

    constexpr int SM256 = 2 * (256 * 128 + 3 * 16384);   // 163840
    constexpr int SM128 = 2 * (128 * 128 + 3 * 16384);   // 131072
    cudaFuncSetAttribute((const void*)layer_hmma<F_INDIM, H1, 256, false, true>,
                         cudaFuncAttributeMaxDynamicSharedMemorySize, SM256);
    cudaFuncSetAttribute((const void*)layer_hmma<H1, H2, 256, false, false>,
                         cudaFuncAttributeMaxDynamicSharedMemorySize, SM256);
    cudaFuncSetAttribute((const void*)layer_hmma<H2, H3, 128, true, false>,
                         cudaFuncAttributeMaxDynamicSharedMemorySize, SM128);

    // encoder (512 blocks x 1024 thr) + weight splits (128 blocks), one launch
    encode_split_kernel<<<512 + 128, 1024>>>(x, spk0, W1, W2, W3, w1s, w2s, w3s);

    layer_hmma<F_INDIM, H1, 256, false, true>
        <<<dim3(M_ROWS / 256, H1 / 128), 512, SM256>>>(spk0, w1s, b1, spk1, nullptr);
    layer_hmma<H1, H2, 256, false, false>
        <<<dim3(M_ROWS / 256, H2 / 128), 512, SM256>>>(spk1, w2s, b2, spk2, nullptr);
    layer_hmma<H2, H3, 128, true, false>
        <<<dim3(M_ROWS / 128, H3 / 128), 512, SM128>>>(spk2, w3s, b3, nullptr, out);
}

// round 15
// speedup vs baseline: 1.4495x; 1.0957x over previous
#include <cuda_runtime.h>
#include <cuda_bf16.h>
#include <cstdint>

#define T_STEPS 32
#define B_SZ    512
#define S_SZ    64
#define F_INDIM 128
#define H1      256
#define H2      256
#define H3      128
#define M_ROWS  (T_STEPS * B_SZ)   // 16384

__device__ __nv_bfloat16 g_spk0[M_ROWS * F_INDIM];
__device__ __nv_bfloat16 g_spk1[M_ROWS * H1];
__device__ __nv_bfloat16 g_spk2[M_ROWS * H2];
__device__ __nv_bfloat16 g_W1s[3 * H1 * F_INDIM];   // [split][h][i]
__device__ __nv_bfloat16 g_W2s[3 * H2 * H1];
__device__ __nv_bfloat16 g_W3s[3 * H3 * H2];

__device__ __forceinline__ uint32_t smem_u32(const void* p) {
    uint32_t a;
    asm("{ .reg .u64 t; cvta.to.shared.u64 t, %1; cvt.u32.u64 %0, t; }" : "=r"(a) : "l"(p));
    return a;
}
__device__ __forceinline__ void ldsm4(uint32_t& r0, uint32_t& r1, uint32_t& r2,
                                      uint32_t& r3, uint32_t addr) {
    asm volatile("ldmatrix.sync.aligned.m8n8.x4.shared.b16 {%0,%1,%2,%3}, [%4];"
                 : "=r"(r0), "=r"(r1), "=r"(r2), "=r"(r3) : "r"(addr));
}
__device__ __forceinline__ void mma16816(float* c, const uint32_t* a,
                                         uint32_t b0, uint32_t b1) {
    asm volatile(
        "mma.sync.aligned.m16n8k16.row.col.f32.bf16.bf16.f32 "
        "{%0,%1,%2,%3}, {%4,%5,%6,%7}, {%8,%9}, {%0,%1,%2,%3};"
        : "+f"(c[0]), "+f"(c[1]), "+f"(c[2]), "+f"(c[3])
        : "r"(a[0]), "r"(a[1]), "r"(a[2]), "r"(a[3]), "r"(b0), "r"(b1));
}
__device__ __forceinline__ void cp16(uint32_t dst, const void* src) {
    asm volatile("cp.async.cg.shared.global [%0], [%1], 16;" :: "r"(dst), "l"(src));
}
#define CP_COMMIT() asm volatile("cp.async.commit_group;" ::: "memory")
#define CP_WAIT(n)  asm volatile("cp.async.wait_group %0;" :: "n"(n) : "memory")

// ---------------------------------------------------------------------------
// Merged encoder (R6/R11 champion version, frozen) + weight-split kernel.
//   blocks [0, 512):   latency encoder (one block per batch element)
//   blocks [512, 768): bf16 3-way weight splits
// ---------------------------------------------------------------------------
__global__ void __launch_bounds__(512)
encode_split_kernel(const float* __restrict__ x, __nv_bfloat16* __restrict__ out,
                    const float* __restrict__ W1, const float* __restrict__ W2,
                    const float* __restrict__ W3,
                    __nv_bfloat16* __restrict__ o1, __nv_bfloat16* __restrict__ o2,
                    __nv_bfloat16* __restrict__ o3) {
    const int tid = threadIdx.x;

    if (blockIdx.x >= 512) {    // ---- weight-split blocks ----
        const int n1 = H1 * F_INDIM, n2 = H2 * H1, n3 = H3 * H2;
        int idx = (blockIdx.x - 512) * 512 + tid;
        const float* W; __nv_bfloat16* o; int n, i;
        if (idx < n1)                { W = W1; o = o1; n = n1; i = idx; }
        else if (idx < n1 + n2)      { W = W2; o = o2; n = n2; i = idx - n1; }
        else if (idx < n1 + n2 + n3) { W = W3; o = o3; n = n3; i = idx - n1 - n2; }
        else return;
        float w = W[i];
        __nv_bfloat16 h1 = __float2bfloat16_rn(w);
        float r1 = w - __bfloat162float(h1);
        __nv_bfloat16 h2 = __float2bfloat16_rn(r1);
        float r2 = r1 - __bfloat162float(h2);
        o[i] = h1; o[n + i] = h2; o[2 * n + i] = __float2bfloat16_rn(r2);
        return;
    }

    // ---- encoder blocks (R6 version verbatim) ----
    const int b = blockIdx.x;
    const int f = tid >> 2;
    const int j = tid & 3;

    const float* xp = x + (size_t)b * (S_SZ * F_INDIM) + f;

    float mn = 1e30f, mx = -1e30f;
    unsigned mask = 0;
#pragma unroll
    for (int s = 0; s < 16; ++s) {
        float raw = xp[(j * 16 + s) * F_INDIM];
        float g = (raw < 0.75f) ? 0.0f : raw;
        mn = fminf(mn, g);
        mx = fmaxf(mx, g);
        mask |= (g != 0.0f) ? (1u << s) : 0u;
    }
    mn = fminf(mn, __shfl_xor_sync(0xFFFFFFFFu, mn, 1));
    mn = fminf(mn, __shfl_xor_sync(0xFFFFFFFFu, mn, 2));
    mx = fmaxf(mx, __shfl_xor_sync(0xFFFFFFFFu, mx, 1));
    mx = fmaxf(mx, __shfl_xor_sync(0xFFFFFFFFu, mx, 2));

    float denom = mx - mn + 1e-8f;
    const float TMAX = 11.512935464920229f;

    unsigned pk[8];
#pragma unroll
    for (int i = 0; i < 8; ++i) pk[i] = 0u;

    int zc = 16 - __popc(mask);
    if (zc) {
        float xn = (0.0f - mn) / denom;
        float d  = fmaxf(xn, 0.0100001f);
        float lg = logf(d / (d - 0.01f));
        float tr = rintf((lg * 31.0f) / TMAX);
        tr = fminf(fmaxf(tr, 0.0f), 31.0f);
        int t = (int)tr;
        pk[t >> 2] += (unsigned)zc << ((t & 3) * 8);
    }
    while (mask) {
        int s = __ffs(mask) - 1;
        mask &= mask - 1;
        float v  = xp[(j * 16 + s) * F_INDIM];
        float xn = (v - mn) / denom;
        float d  = fmaxf(xn, 0.0100001f);
        float lg = logf(d / (d - 0.01f));
        float tr = rintf((lg * 31.0f) / TMAX);
        tr = fminf(fmaxf(tr, 0.0f), 31.0f);
        int t = (int)tr;
        pk[t >> 2] += 1u << ((t & 3) * 8);
    }

#pragma unroll
    for (int i = 0; i < 8; ++i) {
        pk[i] += __shfl_xor_sync(0xFFFFFFFFu, pk[i], 1);
        pk[i] += __shfl_xor_sync(0xFFFFFFFFu, pk[i], 2);
    }
#pragma unroll
    for (int i = 0; i < 8; ++i) {
        int t = j * 8 + i;
        unsigned c = (pk[t >> 2] >> ((t & 3) * 8)) & 0xFFu;
        out[((size_t)b * T_STEPS + t) * F_INDIM + f] =
            __float2bfloat16_rn((float)c * (1.0f / 64.0f));
    }
}

// ---------------------------------------------------------------------------
// Fused HMMA GEMM + LIF — R11 champion compute with an N-tile parameter TN.
// Tile TM x TN, 512 threads (16 warps: 4m x 4n), warp tile (TM/4)m x (TN/4)n.
// KC=64, register-double-buffered SWP over 12 steps.
// ONESHOT (layer 1): stage all K upfront. Else cp.async 2-stage.
// ---------------------------------------------------------------------------
template <int IN, int H, int TM, int TN, bool TMAJ, bool ONESHOT>
__global__ void __launch_bounds__(512, 1)
layer_hmma(const __nv_bfloat16* __restrict__ in,
           const __nv_bfloat16* __restrict__ Wsp,
           const float* __restrict__ bias,
           __nv_bfloat16* __restrict__ out_bf,
           float* __restrict__ out_f) {
    constexpr int WN      = TN / 4;            // warp n-tile
    constexpr int NB      = WN / 16;           // ldsm x4 B loads per step
    constexpr int MB      = TM / 64;           // m16 frags per warp
    constexpr int A_BYTES = TM * 128;          // TM rows x 64k bf16
    constexpr int B_SPLIT = TN * 128;          // TN rows x 64k bf16
    constexpr int SS      = A_BYTES + 3 * B_SPLIT;
    constexpr int NCH     = IN / 64;
    constexpr int CSTR    = TN + 4;            // scur row stride (floats)

    extern __shared__ __align__(1024) char smem[];
    const uint32_t sbase = smem_u32(smem);

    const int tid  = threadIdx.x;
    const int lane = tid & 31;
    const int wrp  = tid >> 5;
    const int wm   = wrp & 3;
    const int wn   = wrp >> 2;
    const int r0   = blockIdx.x * TM;
    const int N0   = blockIdx.y * TN;

    const int la_row = lane & 15;
    const int la_ch  = lane >> 4;
    const int lb_row = lane & 7;
    const int lb_ns  = lane >> 4;
    const int lb_ch  = (lane >> 3) & 1;

    int mrow[MB], nrow[NB];
#pragma unroll
    for (int mb = 0; mb < MB; ++mb) mrow[mb] = wm * (TM / 4) + mb * 16 + la_row;
#pragma unroll
    for (int p = 0; p < NB; ++p) nrow[p] = wn * WN + p * 16 + lb_ns * 8 + lb_row;

    const __nv_bfloat16* Ag = in + (size_t)r0 * IN;

    auto issue_stage = [&](int ch, int buf) {
        const uint32_t dstA = sbase + buf * SS;
#pragma unroll
        for (int it = 0; it < TM / 64; ++it) {
            int v = tid + it * 512, m = v >> 3, kv = v & 7;
            uint32_t off = (uint32_t)(m * 128 + kv * 16);
            off ^= (off >> 3) & 0x70;
            cp16(dstA + off, Ag + (size_t)m * IN + ch * 64 + kv * 8);
        }
        const uint32_t dstB = dstA + A_BYTES;
#pragma unroll
        for (int it = 0; it < 3 * TN * 8 / 512; ++it) {
            int v = tid + it * 512;
            int s = v / (TN * 8), w = v % (TN * 8), n = w >> 3, kv = w & 7;
            uint32_t off = (uint32_t)(n * 128 + kv * 16);
            off ^= (off >> 3) & 0x70;
            cp16(dstB + s * B_SPLIT + off,
                 Wsp + (size_t)s * H * IN + (size_t)(N0 + n) * IN + ch * 64 + kv * 8);
        }
        CP_COMMIT();
    };

    float c[MB][NB * 2][4];
#pragma unroll
    for (int mb = 0; mb < MB; ++mb)
#pragma unroll
        for (int nb = 0; nb < NB * 2; ++nb)
#pragma unroll
            for (int q = 0; q < 4; ++q) c[mb][nb][q] = 0.0f;

    auto compute_chunk = [&](uint32_t bufA, uint32_t bufB) {
        uint32_t aF[2][MB][4];
        uint32_t bF[2][NB][4];

        auto loadA = [&](int ks, int pb) {
#pragma unroll
            for (int mb = 0; mb < MB; ++mb) {
                uint32_t off = (uint32_t)(mrow[mb] * 128 +
                               (((ks * 2 + la_ch) * 16) ^ ((mrow[mb] & 7) << 4)));
                ldsm4(aF[pb][mb][0], aF[pb][mb][1], aF[pb][mb][2], aF[pb][mb][3],
                      bufA + off);
            }
        };
        auto loadB = [&](int ks, int s, int pb) {
#pragma unroll
            for (int p = 0; p < NB; ++p) {
                uint32_t off = (uint32_t)(nrow[p] * 128 +
                               (((ks * 2 + lb_ch) * 16) ^ ((nrow[p] & 7) << 4)));
                ldsm4(bF[pb][p][0], bF[pb][p][1], bF[pb][p][2], bF[pb][p][3],
                      bufB + s * B_SPLIT + off);
            }
        };

        loadA(0, 0);
        loadB(0, 0, 0);
#pragma unroll
        for (int u = 0; u < 12; ++u) {
            const int ks = u / 3;
            const int pb = u & 1;
            if (u < 11) {
                const int un = u + 1;
                const int ksn = un / 3, sn = un - ksn * 3;
                loadB(ksn, sn, un & 1);
                if (sn == 0) loadA(ksn, ksn & 1);
            }
#pragma unroll
            for (int p = 0; p < NB; ++p) {
#pragma unroll
                for (int mb = 0; mb < MB; ++mb) {
                    mma16816(c[mb][2 * p + 0], aF[ks & 1][mb], bF[pb][p][0], bF[pb][p][1]);
                    mma16816(c[mb][2 * p + 1], aF[ks & 1][mb], bF[pb][p][2], bF[pb][p][3]);
                }
            }
        }
    };

    if (ONESHOT) {
#pragma unroll
        for (int ch = 0; ch < NCH; ++ch) issue_stage(ch, ch);
        CP_WAIT(0);
        __syncthreads();
#pragma unroll
        for (int ch = 0; ch < NCH; ++ch)
            compute_chunk(sbase + ch * SS, sbase + ch * SS + A_BYTES);
        __syncthreads();
    } else {
        issue_stage(0, 0);
#pragma unroll 1
        for (int ch = 0; ch < NCH; ++ch) {
            if (ch + 1 < NCH) {
                issue_stage(ch + 1, (ch + 1) & 1);
                CP_WAIT(1);
            } else {
                CP_WAIT(0);
            }
            __syncthreads();
            const uint32_t bufA = sbase + (ch & 1) * SS;
            compute_chunk(bufA, bufA + A_BYTES);
            __syncthreads();
        }
    }

    // ---- epilogue: C frags -> smem [TM m][CSTR stride] f32 ----
    float* scur = (float*)smem;
#pragma unroll
    for (int mb = 0; mb < MB; ++mb)
#pragma unroll
        for (int nb = 0; nb < NB * 2; ++nb) {
            int row = wm * (TM / 4) + mb * 16 + (lane >> 2);
            int col = wn * WN + nb * 8 + 2 * (lane & 3);
            *(float2*)&scur[(size_t)row * CSTR + col] =
                make_float2(c[mb][nb][0], c[mb][nb][1]);
            *(float2*)&scur[(size_t)(row + 8) * CSTR + col] =
                make_float2(c[mb][nb][2], c[mb][nb][3]);
        }
    __syncthreads();

    // ---- fused LIF scan: (TM/32)*TN tasks over 512 threads ----
#pragma unroll
    for (int task = tid; task < (TM / 32) * TN; task += 512) {
        const int bl = task / TN;
        const int h  = task % TN;
        const float bv = bias[N0 + h];
        const int bglob = blockIdx.x * (TM / 32) + bl;
        float mem = 0.0f;
#pragma unroll
        for (int t = 0; t < T_STEPS; ++t) {
            float a2  = scur[(size_t)(bl * 32 + t) * CSTR + h];
            float cur = __fadd_rn(a2, bv);
            float r   = (mem > 1.0f) ? 1.0f : 0.0f;
            mem = __fsub_rn(__fadd_rn(__fmul_rn(0.9f, mem), cur), r);
            float spk = (mem > 1.0f) ? 1.0f : 0.0f;
            if (TMAJ) {
                out_f[((size_t)t * B_SZ + bglob) * H + N0 + h] = spk;
            } else {
                out_bf[(size_t)(r0 + bl * 32 + t) * H + N0 + h] = __float2bfloat16_rn(spk);
            }
        }
    }
}

// ---------------------------------------------------------------------------
extern "C" void kernel_launch(void* const* d_in, const int* in_sizes, int n_in,
                              void* d_out, int out_size) {
    const float* x  = (const float*)d_in[0];
    const float* W1 = (const float*)d_in[1];
    const float* b1 = (const float*)d_in[2];
    const float* W2 = (const float*)d_in[3];
    const float* b2 = (const float*)d_in[4];
    const float* W3 = (const float*)d_in[5];
    const float* b3 = (const float*)d_in[6];
    float* out = (float*)d_out;

    __nv_bfloat16 *spk0, *spk1, *spk2, *w1s, *w2s, *w3s;
    cudaGetSymbolAddress((void**)&spk0, g_spk0);
    cudaGetSymbolAddress((void**)&spk1, g_spk1);
    cudaGetSymbolAddress((void**)&spk2, g_spk2);
    cudaGetSymbolAddress((void**)&w1s, g_W1s);
    cudaGetSymbolAddress((void**)&w2s, g_W2s);
    cudaGetSymbolAddress((void**)&w3s, g_W3s);

    // L1/L2: TM=256, TN=128 (champion). L3: TM=256, TN=64 (L2 geometry, MB=4).
    constexpr int SS128 = 256 * 128 + 3 * 128 * 128;   // 81920
    constexpr int SS64  = 256 * 128 + 3 * 64 * 128;    // 57344
    constexpr int SM_12 = 2 * SS128;                   // 163840
    constexpr int SC64  = 256 * 68 * 4;                // 69632 (epilogue)
    constexpr int SM_3  = (2 * SS64 > SC64) ? 2 * SS64 : SC64;   // 114688

    cudaFuncSetAttribute((const void*)layer_hmma<F_INDIM, H1, 256, 128, false, true>,
                         cudaFuncAttributeMaxDynamicSharedMemorySize, SM_12);
    cudaFuncSetAttribute((const void*)layer_hmma<H1, H2, 256, 128, false, false>,
                         cudaFuncAttributeMaxDynamicSharedMemorySize, SM_12);
    cudaFuncSetAttribute((const void*)layer_hmma<H2, H3, 256, 64, true, false>,
                         cudaFuncAttributeMaxDynamicSharedMemorySize, SM_3);

    // encoder (512 blocks) + weight splits (256 blocks), one launch
    encode_split_kernel<<<512 + 256, 512>>>(x, spk0, W1, W2, W3, w1s, w2s, w3s);

    layer_hmma<F_INDIM, H1, 256, 128, false, true>
        <<<dim3(M_ROWS / 256, H1 / 128), 512, SM_12>>>(spk0, w1s, b1, spk1, nullptr);
    layer_hmma<H1, H2, 256, 128, false, false>
        <<<dim3(M_ROWS / 256, H2 / 128), 512, SM_12>>>(spk1, w2s, b2, spk2, nullptr);
    layer_hmma<H2, H3, 256, 64, true, false>
        <<<dim3(M_ROWS / 256, H3 / 64), 512, SM_3>>>(spk2, w3s, b3, nullptr, out);
}

// round 16
// speedup vs baseline: 1.4755x; 1.0180x over previous
#include <cuda_runtime.h>
#include <cuda_bf16.h>
#include <cstdint>

#define T_STEPS 32
#define B_SZ    512
#define S_SZ    64
#define F_INDIM 128
#define H1      256
#define H2      256
#define H3      128
#define M_ROWS  (T_STEPS * B_SZ)   // 16384

__device__ __nv_bfloat16 g_spk0[M_ROWS * F_INDIM];
__device__ __nv_bfloat16 g_spk1[M_ROWS * H1];
__device__ __nv_bfloat16 g_spk2[M_ROWS * H2];
__device__ __nv_bfloat16 g_W1s[3 * H1 * F_INDIM];   // [split][h][i]
__device__ __nv_bfloat16 g_W2s[3 * H2 * H1];
__device__ __nv_bfloat16 g_W3s[3 * H3 * H2];

__device__ __forceinline__ uint32_t smem_u32(const void* p) {
    uint32_t a;
    asm("{ .reg .u64 t; cvta.to.shared.u64 t, %1; cvt.u32.u64 %0, t; }" : "=r"(a) : "l"(p));
    return a;
}
__device__ __forceinline__ void ldsm4(uint32_t& r0, uint32_t& r1, uint32_t& r2,
                                      uint32_t& r3, uint32_t addr) {
    asm volatile("ldmatrix.sync.aligned.m8n8.x4.shared.b16 {%0,%1,%2,%3}, [%4];"
                 : "=r"(r0), "=r"(r1), "=r"(r2), "=r"(r3) : "r"(addr));
}
__device__ __forceinline__ void mma16816(float* c, const uint32_t* a,
                                         uint32_t b0, uint32_t b1) {
    asm volatile(
        "mma.sync.aligned.m16n8k16.row.col.f32.bf16.bf16.f32 "
        "{%0,%1,%2,%3}, {%4,%5,%6,%7}, {%8,%9}, {%0,%1,%2,%3};"
        : "+f"(c[0]), "+f"(c[1]), "+f"(c[2]), "+f"(c[3])
        : "r"(a[0]), "r"(a[1]), "r"(a[2]), "r"(a[3]), "r"(b0), "r"(b1));
}
__device__ __forceinline__ void cp16(uint32_t dst, const void* src) {
    asm volatile("cp.async.cg.shared.global [%0], [%1], 16;" :: "r"(dst), "l"(src));
}
#define CP_COMMIT() asm volatile("cp.async.commit_group;" ::: "memory")
#define CP_WAIT(n)  asm volatile("cp.async.wait_group %0;" :: "n"(n) : "memory")

// ---------------------------------------------------------------------------
// Classification: t = rint(logf(d/(d-0.01))*31/TMAX) clipped to [0,31].
// Fast path uses __logf (MUFU.LG2). |tt_fast - tt_ref| <= ~3e-5 in tt units;
// when tt_fast is further than 1e-3 from the nearest half-integer boundary,
// rint(tt_fast) == rint(tt_ref) provably. Otherwise (~0.4% of values)
// evaluate the reference expression verbatim -> output bit-identical.
// ---------------------------------------------------------------------------
__device__ __forceinline__ int classify_t(float xn) {
    const float TMAX = 11.512935464920229f;
    float d = fmaxf(xn, 0.0100001f);
    float q = d / (d - 0.01f);           // same rn division as reference
    float ttf = (__logf(q) * 31.0f) / TMAX;
    float trf = rintf(ttf);
    float fr  = fabsf(ttf - trf);        // distance to nearest integer
    if (0.5f - fr < 1e-3f) {             // near a rounding boundary: exact path
        float lg = logf(q);
        float tr = rintf((lg * 31.0f) / TMAX);
        tr = fminf(fmaxf(tr, 0.0f), 31.0f);
        return (int)tr;
    }
    trf = fminf(fmaxf(trf, 0.0f), 31.0f);
    return (int)trf;
}

// ---------------------------------------------------------------------------
// Merged encoder (R6 structure, fast-path classify) + weight-split kernel.
//   blocks [0, 512):   latency encoder (one block per batch element)
//   blocks [512, 768): bf16 3-way weight splits
// ---------------------------------------------------------------------------
__global__ void __launch_bounds__(512)
encode_split_kernel(const float* __restrict__ x, __nv_bfloat16* __restrict__ out,
                    const float* __restrict__ W1, const float* __restrict__ W2,
                    const float* __restrict__ W3,
                    __nv_bfloat16* __restrict__ o1, __nv_bfloat16* __restrict__ o2,
                    __nv_bfloat16* __restrict__ o3) {
    const int tid = threadIdx.x;

    if (blockIdx.x >= 512) {    // ---- weight-split blocks ----
        const int n1 = H1 * F_INDIM, n2 = H2 * H1, n3 = H3 * H2;
        int idx = (blockIdx.x - 512) * 512 + tid;
        const float* W; __nv_bfloat16* o; int n, i;
        if (idx < n1)                { W = W1; o = o1; n = n1; i = idx; }
        else if (idx < n1 + n2)      { W = W2; o = o2; n = n2; i = idx - n1; }
        else if (idx < n1 + n2 + n3) { W = W3; o = o3; n = n3; i = idx - n1 - n2; }
        else return;
        float w = W[i];
        __nv_bfloat16 h1 = __float2bfloat16_rn(w);
        float r1 = w - __bfloat162float(h1);
        __nv_bfloat16 h2 = __float2bfloat16_rn(r1);
        float r2 = r1 - __bfloat162float(h2);
        o[i] = h1; o[n + i] = h2; o[2 * n + i] = __float2bfloat16_rn(r2);
        return;
    }

    // ---- encoder blocks ----
    const int b = blockIdx.x;
    const int f = tid >> 2;
    const int j = tid & 3;

    const float* xp = x + (size_t)b * (S_SZ * F_INDIM) + f;

    float mn = 1e30f, mx = -1e30f;
    unsigned mask = 0;
#pragma unroll
    for (int s = 0; s < 16; ++s) {
        float raw = xp[(j * 16 + s) * F_INDIM];
        float g = (raw < 0.75f) ? 0.0f : raw;
        mn = fminf(mn, g);
        mx = fmaxf(mx, g);
        mask |= (g != 0.0f) ? (1u << s) : 0u;
    }
    mn = fminf(mn, __shfl_xor_sync(0xFFFFFFFFu, mn, 1));
    mn = fminf(mn, __shfl_xor_sync(0xFFFFFFFFu, mn, 2));
    mx = fmaxf(mx, __shfl_xor_sync(0xFFFFFFFFu, mx, 1));
    mx = fmaxf(mx, __shfl_xor_sync(0xFFFFFFFFu, mx, 2));

    float denom = mx - mn + 1e-8f;

    unsigned pk[8];
#pragma unroll
    for (int i = 0; i < 8; ++i) pk[i] = 0u;

    int zc = 16 - __popc(mask);
    if (zc) {
        int t = classify_t((0.0f - mn) / denom);
        pk[t >> 2] += (unsigned)zc << ((t & 3) * 8);
    }
    while (mask) {
        int s = __ffs(mask) - 1;
        mask &= mask - 1;
        float v = xp[(j * 16 + s) * F_INDIM];   // L1 hit
        int t = classify_t((v - mn) / denom);
        pk[t >> 2] += 1u << ((t & 3) * 8);
    }

#pragma unroll
    for (int i = 0; i < 8; ++i) {
        pk[i] += __shfl_xor_sync(0xFFFFFFFFu, pk[i], 1);
        pk[i] += __shfl_xor_sync(0xFFFFFFFFu, pk[i], 2);
    }
#pragma unroll
    for (int i = 0; i < 8; ++i) {
        int t = j * 8 + i;
        unsigned c = (pk[t >> 2] >> ((t & 3) * 8)) & 0xFFu;
        out[((size_t)b * T_STEPS + t) * F_INDIM + f] =
            __float2bfloat16_rn((float)c * (1.0f / 64.0f));
    }
}

// ---------------------------------------------------------------------------
// Fused HMMA GEMM + LIF — R15 champion (TN-parameterized), unchanged.
// Tile TM x TN, 512 threads (16 warps: 4m x 4n), warp tile (TM/4)m x (TN/4)n.
// KC=64, register-double-buffered SWP over 12 steps.
// ONESHOT (layer 1): stage all K upfront. Else cp.async 2-stage.
// ---------------------------------------------------------------------------
template <int IN, int H, int TM, int TN, bool TMAJ, bool ONESHOT>
__global__ void __launch_bounds__(512, 1)
layer_hmma(const __nv_bfloat16* __restrict__ in,
           const __nv_bfloat16* __restrict__ Wsp,
           const float* __restrict__ bias,
           __nv_bfloat16* __restrict__ out_bf,
           float* __restrict__ out_f) {
    constexpr int WN      = TN / 4;
    constexpr int NB      = WN / 16;
    constexpr int MB      = TM / 64;
    constexpr int A_BYTES = TM * 128;
    constexpr int B_SPLIT = TN * 128;
    constexpr int SS      = A_BYTES + 3 * B_SPLIT;
    constexpr int NCH     = IN / 64;
    constexpr int CSTR    = TN + 4;

    extern __shared__ __align__(1024) char smem[];
    const uint32_t sbase = smem_u32(smem);

    const int tid  = threadIdx.x;
    const int lane = tid & 31;
    const int wrp  = tid >> 5;
    const int wm   = wrp & 3;
    const int wn   = wrp >> 2;
    const int r0   = blockIdx.x * TM;
    const int N0   = blockIdx.y * TN;

    const int la_row = lane & 15;
    const int la_ch  = lane >> 4;
    const int lb_row = lane & 7;
    const int lb_ns  = lane >> 4;
    const int lb_ch  = (lane >> 3) & 1;

    int mrow[MB], nrow[NB];
#pragma unroll
    for (int mb = 0; mb < MB; ++mb) mrow[mb] = wm * (TM / 4) + mb * 16 + la_row;
#pragma unroll
    for (int p = 0; p < NB; ++p) nrow[p] = wn * WN + p * 16 + lb_ns * 8 + lb_row;

    const __nv_bfloat16* Ag = in + (size_t)r0 * IN;

    auto issue_stage = [&](int ch, int buf) {
        const uint32_t dstA = sbase + buf * SS;
#pragma unroll
        for (int it = 0; it < TM / 64; ++it) {
            int v = tid + it * 512, m = v >> 3, kv = v & 7;
            uint32_t off = (uint32_t)(m * 128 + kv * 16);
            off ^= (off >> 3) & 0x70;
            cp16(dstA + off, Ag + (size_t)m * IN + ch * 64 + kv * 8);
        }
        const uint32_t dstB = dstA + A_BYTES;
#pragma unroll
        for (int it = 0; it < 3 * TN * 8 / 512; ++it) {
            int v = tid + it * 512;
            int s = v / (TN * 8), w = v % (TN * 8), n = w >> 3, kv = w & 7;
            uint32_t off = (uint32_t)(n * 128 + kv * 16);
            off ^= (off >> 3) & 0x70;
            cp16(dstB + s * B_SPLIT + off,
                 Wsp + (size_t)s * H * IN + (size_t)(N0 + n) * IN + ch * 64 + kv * 8);
        }
        CP_COMMIT();
    };

    float c[MB][NB * 2][4];
#pragma unroll
    for (int mb = 0; mb < MB; ++mb)
#pragma unroll
        for (int nb = 0; nb < NB * 2; ++nb)
#pragma unroll
            for (int q = 0; q < 4; ++q) c[mb][nb][q] = 0.0f;

    auto compute_chunk = [&](uint32_t bufA, uint32_t bufB) {
        uint32_t aF[2][MB][4];
        uint32_t bF[2][NB][4];

        auto loadA = [&](int ks, int pb) {
#pragma unroll
            for (int mb = 0; mb < MB; ++mb) {
                uint32_t off = (uint32_t)(mrow[mb] * 128 +
                               (((ks * 2 + la_ch) * 16) ^ ((mrow[mb] & 7) << 4)));
                ldsm4(aF[pb][mb][0], aF[pb][mb][1], aF[pb][mb][2], aF[pb][mb][3],
                      bufA + off);
            }
        };
        auto loadB = [&](int ks, int s, int pb) {
#pragma unroll
            for (int p = 0; p < NB; ++p) {
                uint32_t off = (uint32_t)(nrow[p] * 128 +
                               (((ks * 2 + lb_ch) * 16) ^ ((nrow[p] & 7) << 4)));
                ldsm4(bF[pb][p][0], bF[pb][p][1], bF[pb][p][2], bF[pb][p][3],
                      bufB + s * B_SPLIT + off);
            }
        };

        loadA(0, 0);
        loadB(0, 0, 0);
#pragma unroll
        for (int u = 0; u < 12; ++u) {
            const int ks = u / 3;
            const int pb = u & 1;
            if (u < 11) {
                const int un = u + 1;
                const int ksn = un / 3, sn = un - ksn * 3;
                loadB(ksn, sn, un & 1);
                if (sn == 0) loadA(ksn, ksn & 1);
            }
#pragma unroll
            for (int p = 0; p < NB; ++p) {
#pragma unroll
                for (int mb = 0; mb < MB; ++mb) {
                    mma16816(c[mb][2 * p + 0], aF[ks & 1][mb], bF[pb][p][0], bF[pb][p][1]);
                    mma16816(c[mb][2 * p + 1], aF[ks & 1][mb], bF[pb][p][2], bF[pb][p][3]);
                }
            }
        }
    };

    if (ONESHOT) {
#pragma unroll
        for (int ch = 0; ch < NCH; ++ch) issue_stage(ch, ch);
        CP_WAIT(0);
        __syncthreads();
#pragma unroll
        for (int ch = 0; ch < NCH; ++ch)
            compute_chunk(sbase + ch * SS, sbase + ch * SS + A_BYTES);
        __syncthreads();
    } else {
        issue_stage(0, 0);
#pragma unroll 1
        for (int ch = 0; ch < NCH; ++ch) {
            if (ch + 1 < NCH) {
                issue_stage(ch + 1, (ch + 1) & 1);
                CP_WAIT(1);
            } else {
                CP_WAIT(0);
            }
            __syncthreads();
            const uint32_t bufA = sbase + (ch & 1) * SS;
            compute_chunk(bufA, bufA + A_BYTES);
            __syncthreads();
        }
    }

    // ---- epilogue: C frags -> smem [TM m][CSTR stride] f32 ----
    float* scur = (float*)smem;
#pragma unroll
    for (int mb = 0; mb < MB; ++mb)
#pragma unroll
        for (int nb = 0; nb < NB * 2; ++nb) {
            int row = wm * (TM / 4) + mb * 16 + (lane >> 2);
            int col = wn * WN + nb * 8 + 2 * (lane & 3);
            *(float2*)&scur[(size_t)row * CSTR + col] =
                make_float2(c[mb][nb][0], c[mb][nb][1]);
            *(float2*)&scur[(size_t)(row + 8) * CSTR + col] =
                make_float2(c[mb][nb][2], c[mb][nb][3]);
        }
    __syncthreads();

    // ---- fused LIF scan: (TM/32)*TN tasks over 512 threads ----
#pragma unroll
    for (int task = tid; task < (TM / 32) * TN; task += 512) {
        const int bl = task / TN;
        const int h  = task % TN;
        const float bv = bias[N0 + h];
        const int bglob = blockIdx.x * (TM / 32) + bl;
        float mem = 0.0f;
#pragma unroll
        for (int t = 0; t < T_STEPS; ++t) {
            float a2  = scur[(size_t)(bl * 32 + t) * CSTR + h];
            float cur = __fadd_rn(a2, bv);
            float r   = (mem > 1.0f) ? 1.0f : 0.0f;
            mem = __fsub_rn(__fadd_rn(__fmul_rn(0.9f, mem), cur), r);
            float spk = (mem > 1.0f) ? 1.0f : 0.0f;
            if (TMAJ) {
                out_f[((size_t)t * B_SZ + bglob) * H + N0 + h] = spk;
            } else {
                out_bf[(size_t)(r0 + bl * 32 + t) * H + N0 + h] = __float2bfloat16_rn(spk);
            }
        }
    }
}

// ---------------------------------------------------------------------------
extern "C" void kernel_launch(void* const* d_in, const int* in_sizes, int n_in,
                              void* d_out, int out_size) {
    const float* x  = (const float*)d_in[0];
    const float* W1 = (const float*)d_in[1];
    const float* b1 = (const float*)d_in[2];
    const float* W2 = (const float*)d_in[3];
    const float* b2 = (const float*)d_in[4];
    const float* W3 = (const float*)d_in[5];
    const float* b3 = (const float*)d_in[6];
    float* out = (float*)d_out;

    __nv_bfloat16 *spk0, *spk1, *spk2, *w1s, *w2s, *w3s;
    cudaGetSymbolAddress((void**)&spk0, g_spk0);
    cudaGetSymbolAddress((void**)&spk1, g_spk1);
    cudaGetSymbolAddress((void**)&spk2, g_spk2);
    cudaGetSymbolAddress((void**)&w1s, g_W1s);
    cudaGetSymbolAddress((void**)&w2s, g_W2s);
    cudaGetSymbolAddress((void**)&w3s, g_W3s);

    constexpr int SS128 = 256 * 128 + 3 * 128 * 128;   // 81920
    constexpr int SS64  = 256 * 128 + 3 * 64 * 128;    // 57344
    constexpr int SM_12 = 2 * SS128;                   // 163840
    constexpr int SC64  = 256 * 68 * 4;                // 69632 (epilogue)
    constexpr int SM_3  = (2 * SS64 > SC64) ? 2 * SS64 : SC64;   // 114688

    cudaFuncSetAttribute((const void*)layer_hmma<F_INDIM, H1, 256, 128, false, true>,
                         cudaFuncAttributeMaxDynamicSharedMemorySize, SM_12);
    cudaFuncSetAttribute((const void*)layer_hmma<H1, H2, 256, 128, false, false>,
                         cudaFuncAttributeMaxDynamicSharedMemorySize, SM_12);
    cudaFuncSetAttribute((const void*)layer_hmma<H2, H3, 256, 64, true, false>,
                         cudaFuncAttributeMaxDynamicSharedMemorySize, SM_3);

    encode_split_kernel<<<512 + 256, 512>>>(x, spk0, W1, W2, W3, w1s, w2s, w3s);

    layer_hmma<F_INDIM, H1, 256, 128, false, true>
        <<<dim3(M_ROWS / 256, H1 / 128), 512, SM_12>>>(spk0, w1s, b1, spk1, nullptr);
    layer_hmma<H1, H2, 256, 128, false, false>
        <<<dim3(M_ROWS / 256, H2 / 128), 512, SM_12>>>(spk1, w2s, b2, spk2, nullptr);
    layer_hmma<H2, H3, 256, 64, true, false>
        <<<dim3(M_ROWS / 256, H3 / 64), 512, SM_3>>>(spk2, w3s, b3, nullptr, out);
}

// round 17
// speedup vs baseline: 1.4934x; 1.0121x over previous
#include <cuda_runtime.h>
#include <cuda_bf16.h>
#include <cstdint>

#define T_STEPS 32
#define B_SZ    512
#define S_SZ    64
#define F_INDIM 128
#define H1      256
#define H2      256
#define H3      128
#define M_ROWS  (T_STEPS * B_SZ)   // 16384

__device__ __nv_bfloat16 g_spk0[M_ROWS * F_INDIM];
__device__ __nv_bfloat16 g_spk1[M_ROWS * H1];
__device__ __nv_bfloat16 g_spk2[M_ROWS * H2];
__device__ __nv_bfloat16 g_W1s[3 * H1 * F_INDIM];   // [split][h][i]
__device__ __nv_bfloat16 g_W2s[3 * H2 * H1];
__device__ __nv_bfloat16 g_W3s[3 * H3 * H2];

__device__ __forceinline__ uint32_t smem_u32(const void* p) {
    uint32_t a;
    asm("{ .reg .u64 t; cvta.to.shared.u64 t, %1; cvt.u32.u64 %0, t; }" : "=r"(a) : "l"(p));
    return a;
}
__device__ __forceinline__ void ldsm4(uint32_t& r0, uint32_t& r1, uint32_t& r2,
                                      uint32_t& r3, uint32_t addr) {
    asm volatile("ldmatrix.sync.aligned.m8n8.x4.shared.b16 {%0,%1,%2,%3}, [%4];"
                 : "=r"(r0), "=r"(r1), "=r"(r2), "=r"(r3) : "r"(addr));
}
__device__ __forceinline__ void mma16816(float* c, const uint32_t* a,
                                         uint32_t b0, uint32_t b1) {
    asm volatile(
        "mma.sync.aligned.m16n8k16.row.col.f32.bf16.bf16.f32 "
        "{%0,%1,%2,%3}, {%4,%5,%6,%7}, {%8,%9}, {%0,%1,%2,%3};"
        : "+f"(c[0]), "+f"(c[1]), "+f"(c[2]), "+f"(c[3])
        : "r"(a[0]), "r"(a[1]), "r"(a[2]), "r"(a[3]), "r"(b0), "r"(b1));
}
__device__ __forceinline__ void cp16(uint32_t dst, const void* src) {
    asm volatile("cp.async.cg.shared.global [%0], [%1], 16;" :: "r"(dst), "l"(src));
}
#define CP_COMMIT() asm volatile("cp.async.commit_group;" ::: "memory")
#define CP_WAIT(n)  asm volatile("cp.async.wait_group %0;" :: "n"(n) : "memory")

// ---------------------------------------------------------------------------
// Classification: t = rint(logf(d/(d-0.01))*31/TMAX) clipped to [0,31].
// Fast path: __fdividef + __logf (total tt error < 1e-4). When tt_fast is
// further than 1e-3 from the nearest rounding boundary, rint matches the
// reference provably; otherwise (~0.4%) evaluate the reference expression
// verbatim (rn division + logf) -> output bit-identical.
// ---------------------------------------------------------------------------
__device__ __forceinline__ int classify_t(float xn) {
    const float TMAX = 11.512935464920229f;
    float d = fmaxf(xn, 0.0100001f);
    float qf = __fdividef(d, d - 0.01f);
    float ttf = (__logf(qf) * 31.0f) / TMAX;
    float trf = rintf(ttf);
    float fr  = fabsf(ttf - trf);
    if (0.5f - fr < 1e-3f) {             // near a boundary: exact reference path
        float q  = d / (d - 0.01f);      // rn division, as in reference
        float lg = logf(q);
        float tr = rintf((lg * 31.0f) / TMAX);
        tr = fminf(fmaxf(tr, 0.0f), 31.0f);
        return (int)tr;
    }
    trf = fminf(fmaxf(trf, 0.0f), 31.0f);
    return (int)trf;
}

// ---------------------------------------------------------------------------
// Merged encoder (R6 structure + fast classify) + weight-split kernel.
//   blocks [0, 512):   latency encoder (one block per batch element)
//   blocks [512, 768): bf16 3-way weight splits
// ---------------------------------------------------------------------------
__global__ void __launch_bounds__(512)
encode_split_kernel(const float* __restrict__ x, __nv_bfloat16* __restrict__ out,
                    const float* __restrict__ W1, const float* __restrict__ W2,
                    const float* __restrict__ W3,
                    __nv_bfloat16* __restrict__ o1, __nv_bfloat16* __restrict__ o2,
                    __nv_bfloat16* __restrict__ o3) {
    const int tid = threadIdx.x;

    if (blockIdx.x >= 512) {    // ---- weight-split blocks ----
        const int n1 = H1 * F_INDIM, n2 = H2 * H1, n3 = H3 * H2;
        int idx = (blockIdx.x - 512) * 512 + tid;
        const float* W; __nv_bfloat16* o; int n, i;
        if (idx < n1)                { W = W1; o = o1; n = n1; i = idx; }
        else if (idx < n1 + n2)      { W = W2; o = o2; n = n2; i = idx - n1; }
        else if (idx < n1 + n2 + n3) { W = W3; o = o3; n = n3; i = idx - n1 - n2; }
        else return;
        float w = W[i];
        __nv_bfloat16 h1 = __float2bfloat16_rn(w);
        float r1 = w - __bfloat162float(h1);
        __nv_bfloat16 h2 = __float2bfloat16_rn(r1);
        float r2 = r1 - __bfloat162float(h2);
        o[i] = h1; o[n + i] = h2; o[2 * n + i] = __float2bfloat16_rn(r2);
        return;
    }

    // ---- encoder blocks ----
    const int b = blockIdx.x;
    const int f = tid >> 2;
    const int j = tid & 3;

    const float* xp = x + (size_t)b * (S_SZ * F_INDIM) + f;

    float mn = 1e30f, mx = -1e30f;
    unsigned mask = 0;
#pragma unroll
    for (int s = 0; s < 16; ++s) {
        float raw = xp[(j * 16 + s) * F_INDIM];
        float g = (raw < 0.75f) ? 0.0f : raw;
        mn = fminf(mn, g);
        mx = fmaxf(mx, g);
        mask |= (g != 0.0f) ? (1u << s) : 0u;
    }
    mn = fminf(mn, __shfl_xor_sync(0xFFFFFFFFu, mn, 1));
    mn = fminf(mn, __shfl_xor_sync(0xFFFFFFFFu, mn, 2));
    mx = fmaxf(mx, __shfl_xor_sync(0xFFFFFFFFu, mx, 1));
    mx = fmaxf(mx, __shfl_xor_sync(0xFFFFFFFFu, mx, 2));

    float denom = mx - mn + 1e-8f;

    unsigned pk[8];
#pragma unroll
    for (int i = 0; i < 8; ++i) pk[i] = 0u;

    int zc = 16 - __popc(mask);
    if (zc) {
        int t = classify_t((0.0f - mn) / denom);
        pk[t >> 2] += (unsigned)zc << ((t & 3) * 8);
    }
    while (mask) {
        int s = __ffs(mask) - 1;
        mask &= mask - 1;
        float v = xp[(j * 16 + s) * F_INDIM];   // L1 hit
        int t = classify_t((v - mn) / denom);
        pk[t >> 2] += 1u << ((t & 3) * 8);
    }

#pragma unroll
    for (int i = 0; i < 8; ++i) {
        pk[i] += __shfl_xor_sync(0xFFFFFFFFu, pk[i], 1);
        pk[i] += __shfl_xor_sync(0xFFFFFFFFu, pk[i], 2);
    }
#pragma unroll
    for (int i = 0; i < 8; ++i) {
        int t = j * 8 + i;
        unsigned c = (pk[t >> 2] >> ((t & 3) * 8)) & 0xFFu;
        out[((size_t)b * T_STEPS + t) * F_INDIM + f] =
            __float2bfloat16_rn((float)c * (1.0f / 64.0f));
    }
}

// ---------------------------------------------------------------------------
// Fused HMMA GEMM + LIF — R15/R16 champion (TN-parameterized).
// Tile TM x TN, 512 threads (16 warps: 4m x 4n), warp tile (TM/4)m x (TN/4)n.
// KC=64, register-double-buffered SWP over 12 steps.
// ONESHOT: stage ALL K-chunks upfront (one wait + one barrier).
// ---------------------------------------------------------------------------
template <int IN, int H, int TM, int TN, bool TMAJ, bool ONESHOT>
__global__ void __launch_bounds__(512, 1)
layer_hmma(const __nv_bfloat16* __restrict__ in,
           const __nv_bfloat16* __restrict__ Wsp,
           const float* __restrict__ bias,
           __nv_bfloat16* __restrict__ out_bf,
           float* __restrict__ out_f) {
    constexpr int WN      = TN / 4;
    constexpr int NB      = WN / 16;
    constexpr int MB      = TM / 64;
    constexpr int A_BYTES = TM * 128;
    constexpr int B_SPLIT = TN * 128;
    constexpr int SS      = A_BYTES + 3 * B_SPLIT;
    constexpr int NCH     = IN / 64;
    constexpr int CSTR    = TN + 4;

    extern __shared__ __align__(1024) char smem[];
    const uint32_t sbase = smem_u32(smem);

    const int tid  = threadIdx.x;
    const int lane = tid & 31;
    const int wrp  = tid >> 5;
    const int wm   = wrp & 3;
    const int wn   = wrp >> 2;
    const int r0   = blockIdx.x * TM;
    const int N0   = blockIdx.y * TN;

    const int la_row = lane & 15;
    const int la_ch  = lane >> 4;
    const int lb_row = lane & 7;
    const int lb_ns  = lane >> 4;
    const int lb_ch  = (lane >> 3) & 1;

    int mrow[MB], nrow[NB];
#pragma unroll
    for (int mb = 0; mb < MB; ++mb) mrow[mb] = wm * (TM / 4) + mb * 16 + la_row;
#pragma unroll
    for (int p = 0; p < NB; ++p) nrow[p] = wn * WN + p * 16 + lb_ns * 8 + lb_row;

    const __nv_bfloat16* Ag = in + (size_t)r0 * IN;

    auto issue_stage = [&](int ch, int buf) {
        const uint32_t dstA = sbase + buf * SS;
#pragma unroll
        for (int it = 0; it < TM / 64; ++it) {
            int v = tid + it * 512, m = v >> 3, kv = v & 7;
            uint32_t off = (uint32_t)(m * 128 + kv * 16);
            off ^= (off >> 3) & 0x70;
            cp16(dstA + off, Ag + (size_t)m * IN + ch * 64 + kv * 8);
        }
        const uint32_t dstB = dstA + A_BYTES;
#pragma unroll
        for (int it = 0; it < 3 * TN * 8 / 512; ++it) {
            int v = tid + it * 512;
            int s = v / (TN * 8), w = v % (TN * 8), n = w >> 3, kv = w & 7;
            uint32_t off = (uint32_t)(n * 128 + kv * 16);
            off ^= (off >> 3) & 0x70;
            cp16(dstB + s * B_SPLIT + off,
                 Wsp + (size_t)s * H * IN + (size_t)(N0 + n) * IN + ch * 64 + kv * 8);
        }
        CP_COMMIT();
    };

    float c[MB][NB * 2][4];
#pragma unroll
    for (int mb = 0; mb < MB; ++mb)
#pragma unroll
        for (int nb = 0; nb < NB * 2; ++nb)
#pragma unroll
            for (int q = 0; q < 4; ++q) c[mb][nb][q] = 0.0f;

    auto compute_chunk = [&](uint32_t bufA, uint32_t bufB) {
        uint32_t aF[2][MB][4];
        uint32_t bF[2][NB][4];

        auto loadA = [&](int ks, int pb) {
#pragma unroll
            for (int mb = 0; mb < MB; ++mb) {
                uint32_t off = (uint32_t)(mrow[mb] * 128 +
                               (((ks * 2 + la_ch) * 16) ^ ((mrow[mb] & 7) << 4)));
                ldsm4(aF[pb][mb][0], aF[pb][mb][1], aF[pb][mb][2], aF[pb][mb][3],
                      bufA + off);
            }
        };
        auto loadB = [&](int ks, int s, int pb) {
#pragma unroll
            for (int p = 0; p < NB; ++p) {
                uint32_t off = (uint32_t)(nrow[p] * 128 +
                               (((ks * 2 + lb_ch) * 16) ^ ((nrow[p] & 7) << 4)));
                ldsm4(bF[pb][p][0], bF[pb][p][1], bF[pb][p][2], bF[pb][p][3],
                      bufB + s * B_SPLIT + off);
            }
        };

        loadA(0, 0);
        loadB(0, 0, 0);
#pragma unroll
        for (int u = 0; u < 12; ++u) {
            const int ks = u / 3;
            const int pb = u & 1;
            if (u < 11) {
                const int un = u + 1;
                const int ksn = un / 3, sn = un - ksn * 3;
                loadB(ksn, sn, un & 1);
                if (sn == 0) loadA(ksn, ksn & 1);
            }
#pragma unroll
            for (int p = 0; p < NB; ++p) {
#pragma unroll
                for (int mb = 0; mb < MB; ++mb) {
                    mma16816(c[mb][2 * p + 0], aF[ks & 1][mb], bF[pb][p][0], bF[pb][p][1]);
                    mma16816(c[mb][2 * p + 1], aF[ks & 1][mb], bF[pb][p][2], bF[pb][p][3]);
                }
            }
        }
    };

    if (ONESHOT) {
#pragma unroll
        for (int ch = 0; ch < NCH; ++ch) issue_stage(ch, ch);
        CP_WAIT(0);
        __syncthreads();
#pragma unroll
        for (int ch = 0; ch < NCH; ++ch)
            compute_chunk(sbase + ch * SS, sbase + ch * SS + A_BYTES);
        __syncthreads();
    } else {
        issue_stage(0, 0);
#pragma unroll 1
        for (int ch = 0; ch < NCH; ++ch) {
            if (ch + 1 < NCH) {
                issue_stage(ch + 1, (ch + 1) & 1);
                CP_WAIT(1);
            } else {
                CP_WAIT(0);
            }
            __syncthreads();
            const uint32_t bufA = sbase + (ch & 1) * SS;
            compute_chunk(bufA, bufA + A_BYTES);
            __syncthreads();
        }
    }

    // ---- epilogue: C frags -> smem [TM m][CSTR stride] f32 ----
    float* scur = (float*)smem;
#pragma unroll
    for (int mb = 0; mb < MB; ++mb)
#pragma unroll
        for (int nb = 0; nb < NB * 2; ++nb) {
            int row = wm * (TM / 4) + mb * 16 + (lane >> 2);
            int col = wn * WN + nb * 8 + 2 * (lane & 3);
            *(float2*)&scur[(size_t)row * CSTR + col] =
                make_float2(c[mb][nb][0], c[mb][nb][1]);
            *(float2*)&scur[(size_t)(row + 8) * CSTR + col] =
                make_float2(c[mb][nb][2], c[mb][nb][3]);
        }
    __syncthreads();

    // ---- fused LIF scan: (TM/32)*TN tasks over 512 threads ----
#pragma unroll
    for (int task = tid; task < (TM / 32) * TN; task += 512) {
        const int bl = task / TN;
        const int h  = task % TN;
        const float bv = bias[N0 + h];
        const int bglob = blockIdx.x * (TM / 32) + bl;
        float mem = 0.0f;
#pragma unroll
        for (int t = 0; t < T_STEPS; ++t) {
            float a2  = scur[(size_t)(bl * 32 + t) * CSTR + h];
            float cur = __fadd_rn(a2, bv);
            float r   = (mem > 1.0f) ? 1.0f : 0.0f;
            mem = __fsub_rn(__fadd_rn(__fmul_rn(0.9f, mem), cur), r);
            float spk = (mem > 1.0f) ? 1.0f : 0.0f;
            if (TMAJ) {
                out_f[((size_t)t * B_SZ + bglob) * H + N0 + h] = spk;
            } else {
                out_bf[(size_t)(r0 + bl * 32 + t) * H + N0 + h] = __float2bfloat16_rn(spk);
            }
        }
    }
}

// ---------------------------------------------------------------------------
extern "C" void kernel_launch(void* const* d_in, const int* in_sizes, int n_in,
                              void* d_out, int out_size) {
    const float* x  = (const float*)d_in[0];
    const float* W1 = (const float*)d_in[1];
    const float* b1 = (const float*)d_in[2];
    const float* W2 = (const float*)d_in[3];
    const float* b2 = (const float*)d_in[4];
    const float* W3 = (const float*)d_in[5];
    const float* b3 = (const float*)d_in[6];
    float* out = (float*)d_out;

    __nv_bfloat16 *spk0, *spk1, *spk2, *w1s, *w2s, *w3s;
    cudaGetSymbolAddress((void**)&spk0, g_spk0);
    cudaGetSymbolAddress((void**)&spk1, g_spk1);
    cudaGetSymbolAddress((void**)&spk2, g_spk2);
    cudaGetSymbolAddress((void**)&w1s, g_W1s);
    cudaGetSymbolAddress((void**)&w2s, g_W2s);
    cudaGetSymbolAddress((void**)&w3s, g_W3s);

    constexpr int SS128 = 256 * 128 + 3 * 128 * 128;   // 81920
    constexpr int SS64  = 256 * 128 + 3 * 64 * 128;    // 57344
    constexpr int SM_12   = 2 * SS128;                 // 163840
    constexpr int SM_3_OS = 4 * SS64;                  // 229376 (ONESHOT all-K)
    constexpr int SC64    = 256 * 68 * 4;              // 69632 (epilogue)
    constexpr int SM_3_PL = (2 * SS64 > SC64) ? 2 * SS64 : SC64;   // 114688

    cudaFuncSetAttribute((const void*)layer_hmma<F_INDIM, H1, 256, 128, false, true>,
                         cudaFuncAttributeMaxDynamicSharedMemorySize, SM_12);
    cudaFuncSetAttribute((const void*)layer_hmma<H1, H2, 256, 128, false, false>,
                         cudaFuncAttributeMaxDynamicSharedMemorySize, SM_12);

    // L3 variant selection: ONESHOT needs 229376 B of opt-in smem.
    int dev = 0, max_optin = 0;
    cudaGetDevice(&dev);
    cudaDeviceGetAttribute(&max_optin, cudaDevAttrMaxSharedMemoryPerBlockOptin, dev);
    const bool l3_oneshot = (max_optin >= SM_3_OS);
    if (l3_oneshot) {
        cudaFuncSetAttribute((const void*)layer_hmma<H2, H3, 256, 64, true, true>,
                             cudaFuncAttributeMaxDynamicSharedMemorySize, SM_3_OS);
    } else {
        cudaFuncSetAttribute((const void*)layer_hmma<H2, H3, 256, 64, true, false>,
                             cudaFuncAttributeMaxDynamicSharedMemorySize, SM_3_PL);
    }

    encode_split_kernel<<<512 + 256, 512>>>(x, spk0, W1, W2, W3, w1s, w2s, w3s);

    layer_hmma<F_INDIM, H1, 256, 128, false, true>
        <<<dim3(M_ROWS / 256, H1 / 128), 512, SM_12>>>(spk0, w1s, b1, spk1, nullptr);
    layer_hmma<H1, H2, 256, 128, false, false>
        <<<dim3(M_ROWS / 256, H2 / 128), 512, SM_12>>>(spk1, w2s, b2, spk2, nullptr);
    if (l3_oneshot) {
        layer_hmma<H2, H3, 256, 64, true, true>
            <<<dim3(M_ROWS / 256, H3 / 64), 512, SM_3_OS>>>(spk2, w3s, b3, nullptr, out);
    } else {
        layer_hmma<H2, H3, 256, 64, true, false>
            <<<dim3(M_ROWS / 256, H3 / 64), 512, SM_3_PL>>>(spk2, w3s, b3, nullptr, out);
    }
}